// round 17
// baseline (speedup 1.0000x reference)
#include <cuda_runtime.h>
#include <cstdint>

#define NN   1024
#define DIM  128
#define NH   8
#define ED   16

#define BN   8      // target rows per CTA
#define BM   32     // source nodes per tile
#define KPAD 132    // k/v smem row stride (floats)
#define EFPAD 20    // ef smem row stride (floats), +4r skew in EFOFF
#define PSTRD 36    // p smem per-(h,r) row stride

#define EFOFF(r, mm) (((r)*BM + (mm))*EFPAD + (r)*4)
#define POFF(h, r)   (((h)*8 + (r))*PSTRD + (h)*4)

// ---- attn smem layout (floats) ----
#define OQ    0
#define OWAE  (OQ   + BN*DIM)            // 1024
#define ORED  (OWAE + ED*NH)             // 1152  (2 x 8 x 132 accs partials)
#define OK0   (ORED + 2*8*132)           // 3264
#define OK1   (OK0  + BM*KPAD)           // 7488
#define OV0   (OK1  + BM*KPAD)           // 11712
#define OV1   (OV0  + BM*KPAD)           // 15936
#define OE0   (OV1  + BM*KPAD)           // 20160
#define OE1   (OE0  + 5152)              // 25312
#define OM0   (OE1  + 5152)              // 30464  (mask tile, 8 x 36 ints)
#define OM1   (OM0  + 288)               // 30752
#define OP_   (OM1  + 288)               // 31040
#define SMEM_FLOATS (OP_ + 2336)         // 33376
#define SMEM_BYTES  (SMEM_FLOATS * 4)    // 133504

__device__ __align__(16) float g_q[NN*DIM];
__device__ __align__(16) float g_k[NN*DIM];
__device__ __align__(16) float g_v[NN*DIM];
__device__ __align__(16) float g_att[NN*DIM];

__device__ __forceinline__ void cpa16(uint32_t dst, const void* src) {
    asm volatile("cp.async.cg.shared.global [%0], [%1], 16;\n" :: "r"(dst), "l"(src));
}
__device__ __forceinline__ void cp_commit() { asm volatile("cp.async.commit_group;\n"); }
__device__ __forceinline__ void cp_wait0()  { asm volatile("cp.async.wait_group 0;\n"); }

// ---------------------------------------------------------------------------
// Kernel 1: pre-LayerNorm + Q/K/V projections, split-K.  (unchanged R16)
// ---------------------------------------------------------------------------
__global__ void __launch_bounds__(768) ln_qkv_kernel(const float* __restrict__ x,
    const float* __restrict__ Wq, const float* __restrict__ bq,
    const float* __restrict__ Wk, const float* __restrict__ bk,
    const float* __restrict__ Wv, const float* __restrict__ bv,
    const float* __restrict__ gamma, const float* __restrict__ beta)
{
    __shared__ float hs[4][DIM];
    __shared__ float part[3][4][DIM];
    const int t = threadIdx.x;
    const int lane = t & 31, wid = t >> 5;
    const int r0 = blockIdx.x * 4;

    if (wid < 4) {
        const int r = wid;
        float xv[4], s = 0.f, s2 = 0.f;
        #pragma unroll
        for (int j = 0; j < 4; j++) {
            xv[j] = x[(r0 + r) * DIM + lane + j * 32];
            s += xv[j]; s2 += xv[j] * xv[j];
        }
        #pragma unroll
        for (int o = 16; o; o >>= 1) {
            s  += __shfl_xor_sync(0xffffffffu, s,  o);
            s2 += __shfl_xor_sync(0xffffffffu, s2, o);
        }
        float mu   = s * (1.0f / DIM);
        float var  = s2 * (1.0f / DIM) - mu * mu;
        float rstd = rsqrtf(var + 1e-5f);
        #pragma unroll
        for (int j = 0; j < 4; j++) {
            int c = lane + j * 32;
            hs[r][c] = (xv[j] - mu) * rstd * gamma[c] + beta[c];
        }
    }
    __syncthreads();

    const int g  = t >> 8;
    const int tt = t & 255;
    const int c  = tt & 127;
    const int kh = tt >> 7;
    const float* W = (g == 0) ? Wq : (g == 1) ? Wk : Wv;
    const float* B = (g == 0) ? bq : (g == 1) ? bk : bv;
    float* O       = (g == 0) ? g_q : (g == 1) ? g_k : g_v;

    float acc[4];
    #pragma unroll
    for (int r = 0; r < 4; r++) acc[r] = 0.f;

    const int k0 = kh * 64;
    #pragma unroll 8
    for (int k = k0; k < k0 + 64; k += 4) {
        float w0 = W[(k+0)*DIM + c];
        float w1 = W[(k+1)*DIM + c];
        float w2 = W[(k+2)*DIM + c];
        float w3 = W[(k+3)*DIM + c];
        #pragma unroll
        for (int r = 0; r < 4; r++) {
            float4 hv = *(const float4*)&hs[r][k];
            acc[r] += hv.x*w0 + hv.y*w1 + hv.z*w2 + hv.w*w3;
        }
    }
    if (kh) {
        #pragma unroll
        for (int r = 0; r < 4; r++) part[g][r][c] = acc[r];
    }
    __syncthreads();
    if (!kh) {
        const float bb = B[c];
        const float sc = (g == 0) ? 0.25f : 1.0f;
        #pragma unroll
        for (int r = 0; r < 4; r++)
            O[(r0 + r) * DIM + c] = (acc[r] + part[g][r][c] + bb) * sc;
    }
}

// ---------------------------------------------------------------------------
// Kernel 2: fused edge-biased attention, phase-specialized warps.
// grid 128, block 512 (16 warps). Per tile each warp runs 3 roles:
//  L: warp (mblk=w>>1, g=w&1), lane (r=l>>2, mi=l&3): logits+exp for
//     m = mblk*4+mi, heads 4g..4g+3. k read = 4-row broadcast (1 phase).
//  A: warp col-block 8w (head hA=w>>1), lane (r=l>>2, cp=l&3): accv over all
//     32 m. v read r-broadcast (1 phase); per-(r,h) denominator in-register.
//  S: warp (rS=w>>1, mh=w&1), lane (h=l>>2, eq=l&3): accs over 16 m.
// p layout POFF gives conflict-free stores (L) and 1-phase loads (A,S).
// ---------------------------------------------------------------------------
__global__ void __launch_bounds__(512, 1) attn_kernel(
    const float* __restrict__ ef, const int* __restrict__ mask,
    const float* __restrict__ Wae, const float* __restrict__ bae,
    const float* __restrict__ Wve, const float* __restrict__ bve)
{
    extern __shared__ float sm[];
    float* q_s   = sm + OQ;
    float* wae_s = sm + OWAE;
    float* p_s   = sm + OP_;

    const int t = threadIdx.x;
    const int l = t & 31, w = t >> 5;
    const int nb = blockIdx.x * BN;

    // L-phase ids
    const int gL = w & 1, mblk = w >> 1;
    const int rL = l >> 2, miL = l & 3;
    const int mloc = mblk * 4 + miL;
    // A-phase ids
    const int hA = w >> 1;
    const int rA = l >> 2, cpA = l & 3;
    const int cvA = w * 8 + 2 * cpA;       // within head hA's 16 cols
    // S-phase ids
    const int rS = w >> 1, mhS = w & 1;
    const int hS = l >> 2, eqS = l & 3;

    uint32_t smem_u32 = (uint32_t)__cvta_generic_to_shared(sm);

    // one-time loads
    for (int i = t; i < BN*DIM; i += 512) q_s[i] = g_q[nb*DIM + i];
    for (int i = t; i < ED*NH;  i += 512) wae_s[i] = Wae[i];

    float baer[4];
    #pragma unroll
    for (int hh = 0; hh < 4; hh++) baer[hh] = __ldg(&bae[4*gL + hh]);

    // ---- tile staging via cp.async (k/v/ef/mask) ----
    auto stage = [&](int m0, int buf) {
        const float* ksrc = g_k + m0 * DIM;
        const float* vsrc = g_v + m0 * DIM;
        uint32_t kd = smem_u32 + (uint32_t)(buf ? OK1 : OK0) * 4u;
        uint32_t vd = smem_u32 + (uint32_t)(buf ? OV1 : OV0) * 4u;
        #pragma unroll
        for (int j = 0; j < 2; j++) {
            int ch = t + j * 512;
            int row = ch >> 5, c4 = ch & 31;
            uint32_t off = (uint32_t)(row * KPAD + c4 * 4) * 4u;
            cpa16(kd + off, ksrc + row * DIM + c4 * 4);
            cpa16(vd + off, vsrc + row * DIM + c4 * 4);
        }
        uint32_t ed = smem_u32 + (uint32_t)(buf ? OE1 : OE0) * 4u;
        #pragma unroll
        for (int j = 0; j < 2; j++) {
            int ch = t + j * 512;
            int rr = ch >> 7, c = ch & 127;
            int mi = c >> 2, e4 = c & 3;
            cpa16(ed + (uint32_t)(EFOFF(rr, mi) + e4 * 4) * 4u,
                  ef + ((size_t)(nb + rr) * NN + m0 + mi) * ED + e4 * 4);
        }
        if (t < 64) {
            int rr = t >> 3, c4 = t & 7;
            uint32_t md = smem_u32 + (uint32_t)(buf ? OM1 : OM0) * 4u;
            cpa16(md + (uint32_t)(rr * 36 + c4 * 4) * 4u,
                  mask + (size_t)(nb + rr) * NN + m0 + c4 * 4);
        }
    };

    stage(0, 0);
    cp_commit();

    float2 accv = make_float2(0.f, 0.f);
    float4 accs = make_float4(0.f, 0.f, 0.f, 0.f);
    float  den  = 0.f;

    cp_wait0();
    __syncthreads();   // tile 0 + q_s/wae_s ready

    // hoist q for L-phase (r, head-group) into registers
    float4 qreg[16];
    {
        const float4* qv = (const float4*)(q_s + rL * DIM + 64 * gL);
        #pragma unroll
        for (int i = 0; i < 16; i++) qreg[i] = qv[i];
    }

    for (int mt = 0; mt < NN / BM; mt++) {
        const int cur = mt & 1;
        float* k_s  = sm + (cur ? OK1 : OK0);
        float* v_s  = sm + (cur ? OV1 : OV0);
        float* ef_s = sm + (cur ? OE1 : OE0);
        const int* msk = (const int*)(sm + (cur ? OM1 : OM0));

        if (mt + 1 < NN / BM) { stage((mt + 1) * BM, cur ^ 1); cp_commit(); }

        // ================= L phase: logits + exp =================
        {
            const int mv = msk[rL * 36 + mloc];
            float lg[4];
            #pragma unroll
            for (int hh = 0; hh < 4; hh++) lg[hh] = baer[hh];
            const float4* kv = (const float4*)(k_s + mloc * KPAD + 64 * gL);
            #pragma unroll
            for (int hh = 0; hh < 4; hh++) {
                float4 b0 = kv[hh*4+0], b1 = kv[hh*4+1];
                float4 b2 = kv[hh*4+2], b3 = kv[hh*4+3];
                float4 a0 = qreg[hh*4+0], a1 = qreg[hh*4+1];
                float4 a2 = qreg[hh*4+2], a3 = qreg[hh*4+3];
                lg[hh] += a0.x*b0.x + a0.y*b0.y + a0.z*b0.z + a0.w*b0.w
                        + a1.x*b1.x + a1.y*b1.y + a1.z*b1.z + a1.w*b1.w
                        + a2.x*b2.x + a2.y*b2.y + a2.z*b2.z + a2.w*b2.w
                        + a3.x*b3.x + a3.y*b3.y + a3.z*b3.z + a3.w*b3.w;
            }
            // edge bias
            const float4* efme = (const float4*)(ef_s + EFOFF(rL, mloc));
            float4 e4[4];
            e4[0]=efme[0]; e4[1]=efme[1]; e4[2]=efme[2]; e4[3]=efme[3];
            const float* ee = (const float*)e4;
            #pragma unroll
            for (int e = 0; e < 16; e++) {
                float evv = ee[e];
                float4 ww = *(const float4*)&wae_s[e*8 + 4*gL];
                lg[0] += evv * ww.x;
                lg[1] += evv * ww.y;
                lg[2] += evv * ww.z;
                lg[3] += evv * ww.w;
            }
            #pragma unroll
            for (int hh = 0; hh < 4; hh++) {
                float p = mv ? __expf(lg[hh]) : 0.f;
                p_s[POFF(4*gL + hh, rL) + mloc] = p;
            }
        }
        __syncthreads();   // p visible to all warps

        // ================= A phase: accv (+den) =================
        {
            const float* prow = p_s + POFF(hA, rA);
            #pragma unroll
            for (int mq = 0; mq < 8; mq++) {
                float4 pq = *(const float4*)(prow + mq * 4);
                den += pq.x + pq.y + pq.z + pq.w;
                const float pj[4] = {pq.x, pq.y, pq.z, pq.w};
                #pragma unroll
                for (int j = 0; j < 4; j++) {
                    float2 vv = *(const float2*)(v_s + (mq*4 + j) * KPAD + cvA);
                    accv.x += pj[j] * vv.x;
                    accv.y += pj[j] * vv.y;
                }
            }
        }
        // ================= S phase: accs =================
        {
            const float* prow = p_s + POFF(hS, rS) + mhS * 16;
            const float* efb  = ef_s + EFOFF(rS, 0) + eqS * 4;
            #pragma unroll
            for (int mq = 0; mq < 4; mq++) {
                float4 pq = *(const float4*)(prow + mq * 4);
                const float pj[4] = {pq.x, pq.y, pq.z, pq.w};
                #pragma unroll
                for (int j = 0; j < 4; j++) {
                    int mm = mhS * 16 + mq * 4 + j;
                    float4 ee = *(const float4*)(efb + mm * EFPAD);
                    accs.x += pj[j] * ee.x;
                    accs.y += pj[j] * ee.y;
                    accs.z += pj[j] * ee.z;
                    accs.w += pj[j] * ee.w;
                }
            }
        }

        if (mt + 1 < NN / BM) cp_wait0();
        __syncthreads();   // cur buffers free; next tile landed
    }

    // ---- epilogue ----
    // S warps publish accs partials (raw, unnormalized)
    *(float4*)(sm + ORED + (mhS * 8 + rS) * 132 + hS * 16 + eqS * 4) = accs;
    __syncthreads();

    // A warps own the final output: lane (rA, cpA) -> row nb+rA, cols cvA..+1
    {
        float inv = 1.0f / den;                 // den[rA, hA], in-register
        float2 o;
        float2 b2 = *(const float2*)(bve + cvA);
        o.x = accv.x * inv + b2.x;
        o.y = accv.y * inv + b2.y;
        const float* red0 = sm + ORED + (0 * 8 + rA) * 132 + hA * 16;
        const float* red1 = sm + ORED + (1 * 8 + rA) * 132 + hA * 16;
        #pragma unroll
        for (int e = 0; e < 16; e++) {
            float sh = (red0[e] + red1[e]) * inv;
            float2 wv = *(const float2*)(Wve + e * DIM + cvA);
            o.x += sh * wv.x;
            o.y += sh * wv.y;
        }
        *(float2*)(g_att + (size_t)(nb + rA) * DIM + cvA) = o;
    }
}

// ---------------------------------------------------------------------------
// Kernel 3: output projection + residual.  (unchanged R16)
// ---------------------------------------------------------------------------
__global__ void __launch_bounds__(256) out_proj_kernel(const float* __restrict__ x,
    const float* __restrict__ Wo, const float* __restrict__ bo,
    float* __restrict__ out)
{
    __shared__ float as[4][DIM];
    __shared__ float part[4][DIM];
    const int t = threadIdx.x;
    const int c = t & 127, half = t >> 7;
    const int r0 = blockIdx.x * 4;

    for (int i = t; i < 4*DIM; i += 256)
        as[i >> 7][i & 127] = g_att[r0*DIM + i];
    __syncthreads();

    float acc[4];
    #pragma unroll
    for (int r = 0; r < 4; r++) acc[r] = 0.f;

    const int k0 = half * 64;
    #pragma unroll 4
    for (int k = k0; k < k0 + 64; k += 4) {
        float w0 = Wo[(k+0)*DIM + c];
        float w1 = Wo[(k+1)*DIM + c];
        float w2 = Wo[(k+2)*DIM + c];
        float w3 = Wo[(k+3)*DIM + c];
        #pragma unroll
        for (int r = 0; r < 4; r++) {
            float4 hv = *(const float4*)&as[r][k];
            acc[r] += hv.x*w0 + hv.y*w1 + hv.z*w2 + hv.w*w3;
        }
    }
    if (half) {
        #pragma unroll
        for (int r = 0; r < 4; r++) part[r][c] = acc[r];
    }
    __syncthreads();
    if (!half) {
        const float bv = bo[c];
        #pragma unroll
        for (int r = 0; r < 4; r++)
            out[(r0+r)*DIM + c] = x[(r0+r)*DIM + c] + acc[r] + part[r][c] + bv;
    }
}

// ---------------------------------------------------------------------------
extern "C" void kernel_launch(void* const* d_in, const int* in_sizes, int n_in,
                              void* d_out, int out_size)
{
    const float* x    = (const float*)d_in[0];
    const float* ef   = (const float*)d_in[1];
    const int*   mask = (const int*)d_in[2];
    const float* Wq   = (const float*)d_in[3];
    const float* bq   = (const float*)d_in[4];
    const float* Wk   = (const float*)d_in[5];
    const float* bk   = (const float*)d_in[6];
    const float* Wv   = (const float*)d_in[7];
    const float* bv   = (const float*)d_in[8];
    const float* Wae  = (const float*)d_in[9];
    const float* bae  = (const float*)d_in[10];
    const float* Wve  = (const float*)d_in[11];
    const float* bve  = (const float*)d_in[12];
    const float* Wo   = (const float*)d_in[13];
    const float* bo   = (const float*)d_in[14];
    const float* gamma= (const float*)d_in[15];
    const float* beta = (const float*)d_in[16];
    float* out = (float*)d_out;

    cudaFuncSetAttribute(attn_kernel,
        cudaFuncAttributeMaxDynamicSharedMemorySize, SMEM_BYTES);

    ln_qkv_kernel<<<NN/4, 768>>>(x, Wq, bq, Wk, bk, Wv, bv, gamma, beta);
    attn_kernel<<<NN/BN, 512, SMEM_BYTES>>>(ef, mask, Wae, bae, Wve, bve);
    out_proj_kernel<<<NN/4, 256>>>(x, Wo, bo, out);
}